// round 11
// baseline (speedup 1.0000x reference)
#include <cuda_runtime.h>

#define T_LEN 131072
#define W     26                 // warm-start FIR taps: rho^26 ~ 4e-6
#define T_SEQ 64                 // exact sequential prefix
#define TB    64                 // timesteps per FIR block; (T_LEN-T_SEQ)/TB = 2047
#define TPT   4                  // timesteps per thread (IIR)
#define NGRP  (TB / TPT)         // 16 groups
#define NTH   (NGRP * 6)         // 96 threads (3 warps)
#define N_RIC 16                 // Riccati iterations from P=0 (0.385^16 ~ 2e-7)
#define NROWS (TB + W + 2)       // 92 shared rows
#define SMS   7                  // shared tile row stride (floats)

__global__ __launch_bounds__(NTH)
void kf_kernel(const float* __restrict__ meas,
               const float* __restrict__ Qm,
               const float* __restrict__ Rm,
               float* __restrict__ out) {
    float* est  = out;
    float* pred = out + (size_t)T_LEN * 6;
    float* vel  = out + (size_t)2 * T_LEN * 6;

    // ---------------- block 0: exact sequential transient ----------------
    if (blockIdx.x == 0) {
        const int d = threadIdx.x;
        if (d >= 6) return;
        const float q = Qm[0];
        const float r = Rm[0];
        float m00 = 1.f, m01 = 0.f, m11 = 1.f;   // cov_init = I12 -> M0 = I2
        float m0 = meas[d], m1 = meas[6 + d];
        est [d] = m0;  est [6 + d] = m1;
        pred[d] = m0;  pred[6 + d] = m1;
        vel [d] = m1 - m0;
        float a = m1, b = m0;
#pragma unroll 4
        for (int t = 2; t < T_SEQ; t++) {
            float Mp00 = 4.f * (m00 - m01) + m11 + q;
            float Mp01 = 2.f * m00 - m01;
            float Mp11 = m00;
            float inv  = __fdividef(1.f, Mp00 + r);
            float k1 = Mp00 * inv, k2 = Mp01 * inv;
            m00 = Mp00 - k1 * Mp00;
            m01 = Mp01 - k1 * Mp01;
            m11 = Mp11 - k2 * Mp01;
            float p  = 2.f * a - b;
            float e  = __ldg(&meas[t * 6 + d]) - p;
            float an = fmaf(k1, e, p);
            float bn = fmaf(k2, e, a);
            est [t * 6 + d]       = an;
            pred[t * 6 + d]       = p;
            vel [(t - 1) * 6 + d] = an - bn;
            a = an; b = bn;
        }
        pred[T_SEQ * 6 + d] = 2.f * a - b;       // row T_SEQ: only writer
        return;
    }

    // ---------------- FIR+IIR blocks ----------------
    __shared__ __align__(16) float sm[NROWS * SMS];       // measurement tile
    __shared__ __align__(16) float sE[TB * 6];            // est staging
    __shared__ __align__(16) float sP[TB * 6];            // pred staging
    __shared__ __align__(16) float sV[TB * 6];            // vel staging

    const int t0   = T_SEQ + (blockIdx.x - 1) * TB;       // 64 + f*64
    const int base = t0 - (W + 2);                        // >= 36; fits in-bounds

    // coalesced tile load: NROWS*6 = 552 floats = 276 float2, 3 iters/thread
    {
        const float2* gsrc = (const float2*)(meas + (size_t)base * 6);
        float2* sdst2 = (float2*)nullptr; (void)sdst2;
#pragma unroll
        for (int it = 0; it < 3; it++) {
            int j = threadIdx.x + it * NTH;
            if (j < (NROWS * 6) / 2) {
                float2 v = __ldg(&gsrc[j]);
                int f0 = 2 * j;                           // flat float index
                int row = f0 / 6, col = f0 - row * 6;
                sm[row * SMS + col]     = v.x;            // col, col+1 same row (6 even)
                sm[row * SMS + col + 1] = v.y;
            }
        }
    }

    // warp-uniform Riccati fixed point from P=0 (overlaps the LDGs above)
    const float q = Qm[0], r = Rm[0];
    float m00 = 0.f, m01 = 0.f, m11 = 0.f;
    float k1 = 0.f, k2 = 0.f;
#pragma unroll
    for (int it = 0; it < N_RIC; it++) {
        float Mp00 = 4.f * (m00 - m01) + m11 + q;
        float Mp01 = 2.f * m00 - m01;
        float Mp11 = m00;
        float inv  = __fdividef(1.f, Mp00 + r);
        k1 = Mp00 * inv; k2 = Mp01 * inv;
        m00 = Mp00 - k1 * Mp00;
        m01 = Mp01 - k1 * Mp01;
        m11 = Mp11 - k2 * Mp01;
    }
    const float det = 1.f - k1;                  // det(A) = rho^2
    const float tr  = 2.f * (1.f - k1) + k2;     // trace(A)
    const float c   = __fdividef(k2, det);       // b_t = a_{t-1} + c*(m_t - a_t)

    __syncthreads();

    const int tt = threadIdx.x / 6;
    const int d  = threadIdx.x - tt * 6;
    const int s0 = tt * TPT + (W + 2);           // local row of first output time

    // ---- warm-start: a1 = a_{tf-1}, a2 = a_{tf-2} (32/31-tap shared FIR) ----
    const float* mp = &sm[(s0 - 1) * SMS + d];   // mp[-s*SMS] = m[tf-1-s]
    float a1 = 0.f, a2 = 0.f;
    float wa    = k1;                            // wa_0
    float wn    = det * (2.f * k1 - k2);         // wa_1
    float wprev = 0.f;
    float xfirst = 0.f;
#pragma unroll
    for (int s = 0; s <= W; s++) {               // 27 iterations, fully unrolled
        float x = mp[-s * SMS];
        if (s == 0) xfirst = x;                  // m[tf-1] for the IIR input term
        if (s < W)  a1 = fmaf(wa, x, a1);
        if (s >= 1) a2 = fmaf(wprev, x, a2);
        wprev = wa;
        if (s < W) {                             // advance generator (2 FMA)
            float nx = fmaf(tr, wn, -det * wa);
            wa = wn; wn = nx;
        }
    }

    // ---- IIR: a_t = tr*a_{t-1} - det*a_{t-2} + k1*m_t - k2*m_{t-1} ----
    float xprev = xfirst;
#pragma unroll
    for (int k = 0; k < TPT; k++) {
        float x  = mp[(k + 1) * SMS];            // m[tf+k]
        float a  = fmaf(tr, a1, fmaf(-det, a2, fmaf(k1, x, -k2 * xprev)));
        float bt = fmaf(c, x - a, a1);
        int li = (tt * TPT + k) * 6 + d;
        sE[li] = a;                              // est_t
        sP[li] = 2.f * a - bt;                   // pred_{t+1}
        sV[li] = a - bt;                         // vel row t-1
        a2 = a1; a1 = a; xprev = x;
    }

    __syncthreads();

    // ---- coalesced copy-out ----
    const int nPV = min(TB, T_LEN - 1 - t0);     // 64 except tail block (63)
    // est: 384 floats = 96 float4, 16B-aligned (t0*24 % 16 == 0), always full
    {
        float4* gE = (float4*)(est + (size_t)t0 * 6);
        gE[threadIdx.x] = ((const float4*)sE)[threadIdx.x];
    }
    // pred/vel: 8B-aligned only -> float2; nPV*3 float2 each
    {
        float2* gP = (float2*)(pred + (size_t)(t0 + 1) * 6);
        float2* gV = (float2*)(vel  + (size_t)(t0 - 1) * 6);
        const float2* s2P = (const float2*)sP;
        const float2* s2V = (const float2*)sV;
        const int n2 = nPV * 3;
#pragma unroll
        for (int it = 0; it < 2; it++) {
            int j = threadIdx.x + it * NTH;
            if (j < n2) { gP[j] = s2P[j]; gV[j] = s2V[j]; }
        }
    }
}

// ---------------------------------------------------------------------------
extern "C" void kernel_launch(void* const* d_in, const int* in_sizes, int n_in,
                              void* d_out, int out_size) {
    const float* meas = (const float*)d_in[0];  // (T,6)
    const float* Q    = (const float*)d_in[1];  // (6,6)
    const float* R    = (const float*)d_in[2];  // (6,6)
    float* out = (float*)d_out;

    const int nb = 1 + (T_LEN - T_SEQ) / TB;    // 1 + 2047
    kf_kernel<<<nb, NTH>>>(meas, Q, R, out);
}